// round 11
// baseline (speedup 1.0000x reference)
#include <cuda_runtime.h>
#include <cstdint>

#define T_ 256
#define B_ 64
#define M_ 512
#define N_ 1024
#define NB_REC 128
#define NBD 128         // arrivals per direction barrier (all blocks' halves)

// Scratch: G[dir*3+gate][t][b][n]  (gate order f,i,c)
__device__ float g_G[(size_t)6 * T_ * N_ * B_];
// h double buffer, k-pair-permuted + tf32-rounded: [buf][dir][b][kslot 1024]
__device__ float g_hP[2][2][B_ * N_];
// U packed in mma-fragment order as tf32 bit patterns:
// [dir][tile 128][kq 4][c 8][ks 4][rg 2][lane 32] uint4
__device__ uint4 g_Upk[1u << 21];
// per-step per-dir grid barrier counters (zeroed by k_init every launch)
__device__ unsigned g_bar[2 * T_];

struct PW { const float* p[6]; };
struct PU { const float* U[8]; const float* bia[8]; };

__device__ __forceinline__ uint32_t f2tf(float v) {
  uint32_t u; asm("cvt.rna.tf32.f32 %0, %1;" : "=r"(u) : "f"(v)); return u;
}
__device__ __forceinline__ void mma8(float* c, uint32_t a0, uint32_t a1,
                                     uint32_t a2, uint32_t a3,
                                     uint32_t b0, uint32_t b1) {
  asm volatile(
    "mma.sync.aligned.m16n8k8.row.col.f32.tf32.tf32.f32 "
    "{%0,%1,%2,%3},{%4,%5,%6,%7},{%8,%9},{%0,%1,%2,%3};\n"
    : "+f"(c[0]), "+f"(c[1]), "+f"(c[2]), "+f"(c[3])
    : "r"(a0), "r"(a1), "r"(a2), "r"(a3), "r"(b0), "r"(b1));
}
__device__ __forceinline__ void cpa16(uint32_t d, const void* s) {
  asm volatile("cp.async.cg.shared.global [%0], [%1], 16;" :: "r"(d), "l"(s));
}
__device__ __forceinline__ void barn(int id, int cnt) {
  asm volatile("bar.sync %0, %1;" :: "r"(id), "r"(cnt) : "memory");
}
__device__ __forceinline__ int kperm(int n) {        // pair (k, k+4) adjacent
  return (n & ~7) + ((n & 3) << 1) + ((n >> 2) & 1);
}
__device__ __forceinline__ float sigm_f(float x) {
  return __fdividef(1.f, 1.f + __expf(-x));
}
__device__ __forceinline__ float tanh_f(float x) {
  return 1.f - __fdividef(2.f, __expf(2.f * x) + 1.f);
}

__global__ void k_init(const float* __restrict__ hidden) {
  int i = blockIdx.x * blockDim.x + threadIdx.x;   // 65536 threads
  if (i < B_ * N_) {
    int b = i >> 10, n = i & 1023;
    float v = __uint_as_float(f2tf(hidden[i]));
    g_hP[0][0][b * N_ + kperm(n)] = v;
    g_hP[0][1][b * N_ + kperm(n)] = v;
  }
  if (i < 2 * T_) g_bar[i] = 0;
}

// Pack U into fragment order (one uint4 per thread).
// uint4 = (U_{2rg}[row,k], U_{2rg+1}[row,k], U_{2rg}[row,k+4], U_{2rg+1}[row,k+4])
__global__ void __launch_bounds__(256) k_pack(PU pu) {
  unsigned i = blockIdx.x * 256 + threadIdx.x;
  unsigned lane = i & 31, rg = (i >> 5) & 1, ks = (i >> 6) & 3,
           c = (i >> 8) & 7, kq = (i >> 11) & 3, tile = (i >> 13) & 127,
           dir = (i >> 20) & 1;
  int g4 = lane >> 2, tq = lane & 3;
  int row = tile * 8 + g4;
  int k = kq * 256 + c * 32 + ks * 8 + tq;
  const float* U0 = pu.U[dir * 4 + 2 * rg];
  const float* U1 = pu.U[dir * 4 + 2 * rg + 1];
  uint4 o;
  o.x = f2tf(U0[(size_t)row * N_ + k]);
  o.y = f2tf(U1[(size_t)row * N_ + k]);
  o.z = f2tf(U0[(size_t)row * N_ + k + 4]);
  o.w = f2tf(U1[(size_t)row * N_ + k + 4]);
  g_Upk[i] = o;
}

// ---------------- Phase 1: G[dg][t][b][n] = sum_m x[t_src,b,m] * W[m,n] ----
__device__ __forceinline__ float4 cvt4(float4 v) {
  float4 r;
  r.x = __uint_as_float(f2tf(v.x)); r.y = __uint_as_float(f2tf(v.y));
  r.z = __uint_as_float(f2tf(v.z)); r.w = __uint_as_float(f2tf(v.w));
  return r;
}

__global__ void __launch_bounds__(256) k_gemm_xw(const float* __restrict__ x, PW pw) {
  __shared__ __align__(16) float As[64][36];
  __shared__ __align__(16) float Bs[32][136];
  int tid = threadIdx.x;
  int wid = tid >> 5, lane = tid & 31;
  int g4 = lane >> 2, tq = lane & 3;
  int wm = wid & 1, wn = wid >> 1;
  int n0 = blockIdx.x * 128;
  int t = blockIdx.y;
  int dg = blockIdx.z;
  int dir = dg / 3;
  int t_src = dir ? (T_ - 1 - t) : t;
  const float* W = pw.p[dg];
  const float* xt = x + (size_t)t_src * (B_ * M_);

  float acc[2][4][4];
  #pragma unroll
  for (int a = 0; a < 2; a++)
    #pragma unroll
    for (int b = 0; b < 4; b++)
      #pragma unroll
      for (int cc = 0; cc < 4; cc++) acc[a][b][cc] = 0.f;

  for (int k0 = 0; k0 < M_; k0 += 32) {
    #pragma unroll
    for (int j = 0; j < 2; j++) {
      int i = tid + j * 256;
      int bb = i >> 3, kq = (i & 7) << 2;
      *(float4*)&As[bb][kq] = cvt4(*(const float4*)(xt + bb * M_ + k0 + kq));
    }
    #pragma unroll
    for (int j = 0; j < 4; j++) {
      int i = tid + j * 256;
      int kk = i >> 5, nq = (i & 31) << 2;
      *(float4*)&Bs[kk][nq] = cvt4(*(const float4*)(W + (size_t)(k0 + kk) * N_ + n0 + nq));
    }
    __syncthreads();
    #pragma unroll
    for (int ks = 0; ks < 32; ks += 8) {
      uint32_t af[2][4];
      #pragma unroll
      for (int mt = 0; mt < 2; mt++) {
        int r = wm * 32 + mt * 16 + g4;
        af[mt][0] = __float_as_uint(As[r][ks + tq]);
        af[mt][1] = __float_as_uint(As[r + 8][ks + tq]);
        af[mt][2] = __float_as_uint(As[r][ks + tq + 4]);
        af[mt][3] = __float_as_uint(As[r + 8][ks + tq + 4]);
      }
      #pragma unroll
      for (int nt = 0; nt < 4; nt++) {
        int ccol = wn * 32 + nt * 8 + g4;
        uint32_t b0 = __float_as_uint(Bs[ks + tq][ccol]);
        uint32_t b1 = __float_as_uint(Bs[ks + tq + 4][ccol]);
        #pragma unroll
        for (int mt = 0; mt < 2; mt++)
          mma8(acc[mt][nt], af[mt][0], af[mt][1], af[mt][2], af[mt][3], b0, b1);
      }
    }
    __syncthreads();
  }
  size_t gb = (size_t)(dg * T_ + t) * (N_ * B_);
  #pragma unroll
  for (int mt = 0; mt < 2; mt++) {
    int brow = wm * 32 + mt * 16 + g4;
    #pragma unroll
    for (int nt = 0; nt < 4; nt++) {
      int nc = n0 + wn * 32 + nt * 8 + 2 * tq;
      *(float2*)&g_G[gb + (size_t)brow * N_ + nc] =
          make_float2(acc[mt][nt][0], acc[mt][nt][1]);
      *(float2*)&g_G[gb + (size_t)(brow + 8) * N_ + nc] =
          make_float2(acc[mt][nt][2], acc[mt][nt][3]);
    }
  }
}

// ---------------- Phase 2: persistent recurrent kernel ---------------------
// 512 thr = 2 INDEPENDENT halves of 256; half h runs direction h on tile
// blockIdx.x (8 n-rows). Within a half: 4 warp-pairs, pair kq owns k-slice
// [kq*256, +256) in 8 chunks of 32, staged in a private double buffer.
// Warp rg of a pair: gates {2rg, 2rg+1} (16 U-rows = one m16 tile).
// All sync via named barriers: pair id 1+p (64 thr), half id 9+h (256 thr).
#define BUFW 2560                  // 64 b * 40 words per chunk buffer
#define PAIRW 5120                 // 2 buffers per pair
#define SMEM_BYTES (8 * PAIRW * 4) // 163840
// zs overlaid on each pair's own region after drain: [r 32][cl 66]
#define ZS(p, r, cl) ((p) * PAIRW + (r) * 66 + (cl))

__global__ void __launch_bounds__(512) k_recur(PU pu, float* __restrict__ out) {
  extern __shared__ float sm[];
  uint32_t smb = (uint32_t)__cvta_generic_to_shared(sm);
  int tid = threadIdx.x, lane = tid & 31;
  int h = tid >> 8;                       // = direction
  int ht = tid & 255;                     // half-local tid
  int wid_h = ht >> 5;
  int g4 = lane >> 2, tq = lane & 3;
  int rg = wid_h & 1, kq = wid_h >> 1;
  int pt = rg * 32 + lane;                // pair-local tid 0..63
  int p = h * 4 + kq;                     // pair region index 0..7
  int bar_pair = 1 + p;
  int bar_half = 9 + h;
  int dir = h;
  int bl = blockIdx.x;                    // tile 0..127 (8 n-rows)
  int rn = bl << 3;

  const uint4* upk = g_Upk + ((((size_t)dir * 128 + bl) * 4 + kq) * 2048)
                     + rg * 32 + lane;
  uint32_t pair_smb = smb + p * PAIRW * 4;

  // elementwise ownership (within half): b = ht>>2, n = rn + nn, nn+1
  int b_e = ht >> 2;
  int nn = (ht & 3) << 1;

  float bia[4][2];
  #pragma unroll
  for (int g = 0; g < 4; g++) {
    bia[g][0] = pu.bia[dir * 4 + g][rn + nn];
    bia[g][1] = pu.bia[dir * 4 + g][rn + nn + 1];
  }
  const float* Gb0 = g_G + (size_t)(dir * 3 + 0) * T_ * N_ * B_;
  const float* Gb1 = g_G + (size_t)(dir * 3 + 1) * T_ * N_ * B_;
  const float* Gb2 = g_G + (size_t)(dir * 3 + 2) * T_ * N_ * B_;
  int hslot0 = kperm(rn + nn), hslot1 = kperm(rn + nn + 1);
  unsigned* barp = &g_bar[dir * T_];

  float creg[2] = {0.f, 0.f};

  for (int s = 0; s < T_; ++s) {
    const float* hsrc = g_hP[s & 1][dir];
    const float* hkq = hsrc + kq * 256;

    // stage chunks 0,1 into bufs 0,1 (pair-private)
    #pragma unroll
    for (int c0 = 0; c0 < 2; c0++) {
      #pragma unroll
      for (int j = 0; j < 8; j++) {
        int unit = pt + j * 64;
        int b = unit >> 3, seg = unit & 7;
        cpa16(pair_smb + (c0 * BUFW + b * 40 + seg * 4) * 4,
              hkq + b * N_ + c0 * 32 + seg * 4);
      }
      asm volatile("cp.async.commit_group;");
    }

    // prefetch this step's G (coalesced float2, [t][b][n] layout)
    size_t goff = ((size_t)s * B_ + b_e) * N_ + rn + nn;
    float2 gq0 = __ldg((const float2*)(Gb0 + goff));
    float2 gq1 = __ldg((const float2*)(Gb1 + goff));
    float2 gq2 = __ldg((const float2*)(Gb2 + goff));

    float acc[8][4];
    #pragma unroll
    for (int nt = 0; nt < 8; nt++)
      #pragma unroll
      for (int cc = 0; cc < 4; cc++) acc[nt][cc] = 0.f;

    // 8 chunks x 4 k-steps; one m16 A-tile per warp per k-step
    #pragma unroll 1
    for (int c = 0; c < 8; ++c) {
      if (c < 7) asm volatile("cp.async.wait_group 1;");
      else       asm volatile("cp.async.wait_group 0;");
      barn(bar_pair, 64);                // chunk c visible to both warps

      const float* bb = sm + p * PAIRW + (c & 1) * BUFW + 2 * tq;
      const uint4* up = upk + c * 256;
      #pragma unroll
      for (int ks = 0; ks < 4; ++ks) {
        uint4 A = __ldg(up + ks * 64);
        #pragma unroll
        for (int nt = 0; nt < 8; ++nt) {
          uint2 Bv = *(const uint2*)(bb + (nt * 8 + g4) * 40 + ks * 8);
          mma8(acc[nt], A.x, A.y, A.z, A.w, Bv.x, Bv.y);
        }
      }
      if (c < 6) {
        barn(bar_pair, 64);              // both warps done with buf c&1
        int cn = c + 2;
        #pragma unroll
        for (int j = 0; j < 8; j++) {
          int unit = pt + j * 64;
          int b = unit >> 3, seg = unit & 7;
          cpa16(pair_smb + ((c & 1) * BUFW + b * 40 + seg * 4) * 4,
                hkq + b * N_ + cn * 32 + seg * 4);
        }
        asm volatile("cp.async.commit_group;");
      }
    }

    barn(bar_pair, 64);   // partner drained buf1 -> pair region reusable as zs

    // write k-partials into own pair region: zs[p][gate*8 + n][b]
    {
      int r0 = (2 * rg) * 8 + g4;
      int r1 = (2 * rg + 1) * 8 + g4;
      #pragma unroll
      for (int nt = 0; nt < 8; nt++) {
        int cl = nt * 8 + 2 * tq;
        *(float2*)&sm[ZS(p, r0, cl)] = make_float2(acc[nt][0], acc[nt][1]);
        *(float2*)&sm[ZS(p, r1, cl)] = make_float2(acc[nt][2], acc[nt][3]);
      }
    }
    barn(bar_half, 256);

    // elementwise LSTM cell (2 consecutive n per thread, one b)
    float z[4][2];
    #pragma unroll
    for (int g = 0; g < 4; g++) {
      #pragma unroll
      for (int e = 0; e < 2; e++) {
        float zz = bia[g][e];
        #pragma unroll
        for (int q = 0; q < 4; q++)
          zz += sm[ZS(h * 4 + q, g * 8 + nn + e, b_e)];
        z[g][e] = zz;
      }
    }
    float* hdst = g_hP[(s + 1) & 1][dir];
    int t_out = dir ? (T_ - 1 - s) : s;
    float2 ho;
    #pragma unroll
    for (int e = 0; e < 2; e++) {
      float gf = e ? gq0.y : gq0.x;
      float gi = e ? gq1.y : gq1.x;
      float gc = e ? gq2.y : gq2.x;
      float zf = z[0][e] + gf, zi = z[1][e] + gi;
      float zc = z[2][e] + gc, zo = z[3][e] + gf;   // o reuses gf (ref bug)
      float f  = sigm_f(zf);
      float ig = sigm_f(zi);
      float o  = sigm_f(zo);
      float cn = f * creg[e] + ig * tanh_f(zc);
      creg[e] = cn;
      float hh = o * tanh_f(cn);
      ((float*)&ho)[e] = hh;
      __stcg(hdst + b_e * N_ + (e ? hslot1 : hslot0), __uint_as_float(f2tf(hh)));
    }
    *(float2*)(out + ((size_t)t_out * B_ + b_e) * (2 * N_) +
               (size_t)dir * N_ + rn + nn) = ho;

    // per-direction grid barrier, half-scoped (other half keeps computing)
    if (s < T_ - 1) {
      barn(bar_half, 256);   // all half stores + zs reads done
      if (ht == 0) {
        unsigned v;
        asm volatile("atom.add.acq_rel.gpu.global.u32 %0, [%1], 1;"
                     : "=r"(v) : "l"(&barp[s]) : "memory");
        if (v + 1u < NBD) {
          unsigned w;
          do {
            asm volatile("ld.acquire.gpu.global.u32 %0, [%1];"
                         : "=r"(w) : "l"(&barp[s]) : "memory");
            if (w >= NBD) break;
            __nanosleep(32);
          } while (true);
        }
      }
      barn(bar_half, 256);   // acquire ordering propagates half-wide
    }
  }
}

extern "C" void kernel_launch(void* const* d_in, const int* in_sizes, int n_in,
                              void* d_out, int out_size) {
  const float* x      = (const float*)d_in[0];
  const float* hidden = (const float*)d_in[1];
  PW pw;
  pw.p[0] = (const float*)d_in[2];   // Wf1
  pw.p[1] = (const float*)d_in[3];   // Wi1
  pw.p[2] = (const float*)d_in[4];   // Wc1
  pw.p[3] = (const float*)d_in[13];  // Wf2
  pw.p[4] = (const float*)d_in[14];  // Wi2
  pw.p[5] = (const float*)d_in[15];  // Wc2

  PU pu;  // gate order f,i,c,o
  pu.U[0] = (const float*)d_in[5];   // Uf1
  pu.U[1] = (const float*)d_in[6];   // Ui1
  pu.U[2] = (const float*)d_in[8];   // Uc1
  pu.U[3] = (const float*)d_in[7];   // Uo1
  pu.U[4] = (const float*)d_in[16];  // Uf2
  pu.U[5] = (const float*)d_in[17];  // Ui2
  pu.U[6] = (const float*)d_in[19];  // Uc2
  pu.U[7] = (const float*)d_in[18];  // Uo2
  pu.bia[0] = (const float*)d_in[9];   // bf1
  pu.bia[1] = (const float*)d_in[10];  // bi1
  pu.bia[2] = (const float*)d_in[12];  // bc1
  pu.bia[3] = (const float*)d_in[11];  // bo1
  pu.bia[4] = (const float*)d_in[20];  // bf2
  pu.bia[5] = (const float*)d_in[21];  // bi2
  pu.bia[6] = (const float*)d_in[23];  // bc2
  pu.bia[7] = (const float*)d_in[22];  // bo2

  static int smem_set = 0;
  if (!smem_set) {
    cudaFuncSetAttribute(k_recur, cudaFuncAttributeMaxDynamicSharedMemorySize,
                         SMEM_BYTES);
    smem_set = 1;
  }

  k_init<<<256, 256>>>(hidden);
  k_pack<<<8192, 256>>>(pu);
  k_gemm_xw<<<dim3(8, 256, 6), 256>>>(x, pw);
  k_recur<<<NB_REC, 512, SMEM_BYTES>>>(pu, (float*)d_out);
}

// round 12
// speedup vs baseline: 1.1358x; 1.1358x over previous
#include <cuda_runtime.h>
#include <cstdint>

#define T_ 256
#define B_ 64
#define M_ 512
#define N_ 1024
#define NB_REC 128
#define NBD 64          // blocks per direction (barrier arrivals)

// Scratch: G[dir*3+gate][t][b][n]  (gate order f,i,c)
__device__ float g_G[(size_t)6 * T_ * N_ * B_];
// h double buffer, k-pair-permuted + tf32-rounded: [buf][dir][b][kslot 1024]
__device__ float g_hP[2][2][B_ * N_];
// U packed in mma-fragment order as tf32 bit patterns:
// [dir][tile 64][kq 8][t 16][gate 4][lane 32] uint4
// uint4 = (Ug[n,k], Ug[n+8,k], Ug[n,k+4], Ug[n+8,k+4]),
//   n = tile*16 + g4, k = kq*128 + t*8 + tq
__device__ uint4 g_Upk[1u << 21];
// per-step per-dir grid barrier counters (zeroed by k_init every launch)
__device__ unsigned g_bar[2 * T_];
// per-block release flags, 128B apart: [dir][blk 64][32]
__device__ unsigned g_flag[2][64][32];

struct PW { const float* p[6]; };
struct PU { const float* U[8]; const float* bia[8]; };

__device__ __forceinline__ uint32_t f2tf(float v) {
  uint32_t u; asm("cvt.rna.tf32.f32 %0, %1;" : "=r"(u) : "f"(v)); return u;
}
__device__ __forceinline__ void mma8(float* c, uint32_t a0, uint32_t a1,
                                     uint32_t a2, uint32_t a3,
                                     uint32_t b0, uint32_t b1) {
  asm volatile(
    "mma.sync.aligned.m16n8k8.row.col.f32.tf32.tf32.f32 "
    "{%0,%1,%2,%3},{%4,%5,%6,%7},{%8,%9},{%0,%1,%2,%3};\n"
    : "+f"(c[0]), "+f"(c[1]), "+f"(c[2]), "+f"(c[3])
    : "r"(a0), "r"(a1), "r"(a2), "r"(a3), "r"(b0), "r"(b1));
}
__device__ __forceinline__ void cpa16(uint32_t d, const void* s) {
  asm volatile("cp.async.cg.shared.global [%0], [%1], 16;" :: "r"(d), "l"(s));
}
__device__ __forceinline__ void barp64(int id) {
  asm volatile("bar.sync %0, 64;" :: "r"(id) : "memory");
}
__device__ __forceinline__ int kperm(int n) {        // pair (k, k+4) adjacent
  return (n & ~7) + ((n & 3) << 1) + ((n >> 2) & 1);
}
__device__ __forceinline__ float sigm_f(float x) {
  return __fdividef(1.f, 1.f + __expf(-x));
}
__device__ __forceinline__ float tanh_f(float x) {
  return 1.f - __fdividef(2.f, __expf(2.f * x) + 1.f);
}

__global__ void k_init(const float* __restrict__ hidden) {
  int i = blockIdx.x * blockDim.x + threadIdx.x;   // 65536 threads
  if (i < B_ * N_) {
    int b = i >> 10, n = i & 1023;
    float v = __uint_as_float(f2tf(hidden[i]));
    g_hP[0][0][b * N_ + kperm(n)] = v;
    g_hP[0][1][b * N_ + kperm(n)] = v;
  }
  if (i < 2 * T_) g_bar[i] = 0;
  if (i < 128) g_flag[i >> 6][i & 63][0] = 0;
}

// Pack U into fragment order (one uint4 per thread).
__global__ void __launch_bounds__(256) k_pack(PU pu) {
  unsigned i = blockIdx.x * 256 + threadIdx.x;
  unsigned lane = i & 31, gate = (i >> 5) & 3, t = (i >> 7) & 15,
           kq = (i >> 11) & 7, tile = (i >> 14) & 63, dir = (i >> 20) & 1;
  int g4 = lane >> 2, tq = lane & 3;
  int row = tile * 16 + g4;
  int k = kq * 128 + t * 8 + tq;
  const float* U = pu.U[dir * 4 + gate];
  uint4 o;
  o.x = f2tf(U[(size_t)row * N_ + k]);
  o.y = f2tf(U[(size_t)(row + 8) * N_ + k]);
  o.z = f2tf(U[(size_t)row * N_ + k + 4]);
  o.w = f2tf(U[(size_t)(row + 8) * N_ + k + 4]);
  g_Upk[i] = o;
}

// ---------------- Phase 1: G[dg][t][b][n] = sum_m x[t_src,b,m] * W[m,n] ----
__device__ __forceinline__ float4 cvt4(float4 v) {
  float4 r;
  r.x = __uint_as_float(f2tf(v.x)); r.y = __uint_as_float(f2tf(v.y));
  r.z = __uint_as_float(f2tf(v.z)); r.w = __uint_as_float(f2tf(v.w));
  return r;
}

__global__ void __launch_bounds__(256) k_gemm_xw(const float* __restrict__ x, PW pw) {
  __shared__ __align__(16) float As[64][36];
  __shared__ __align__(16) float Bs[32][136];
  int tid = threadIdx.x;
  int wid = tid >> 5, lane = tid & 31;
  int g4 = lane >> 2, tq = lane & 3;
  int wm = wid & 1, wn = wid >> 1;
  int n0 = blockIdx.x * 128;
  int t = blockIdx.y;
  int dg = blockIdx.z;
  int dir = dg / 3;
  int t_src = dir ? (T_ - 1 - t) : t;
  const float* W = pw.p[dg];
  const float* xt = x + (size_t)t_src * (B_ * M_);

  float acc[2][4][4];
  #pragma unroll
  for (int a = 0; a < 2; a++)
    #pragma unroll
    for (int b = 0; b < 4; b++)
      #pragma unroll
      for (int cc = 0; cc < 4; cc++) acc[a][b][cc] = 0.f;

  for (int k0 = 0; k0 < M_; k0 += 32) {
    #pragma unroll
    for (int j = 0; j < 2; j++) {
      int i = tid + j * 256;
      int bb = i >> 3, kq = (i & 7) << 2;
      *(float4*)&As[bb][kq] = cvt4(*(const float4*)(xt + bb * M_ + k0 + kq));
    }
    #pragma unroll
    for (int j = 0; j < 4; j++) {
      int i = tid + j * 256;
      int kk = i >> 5, nq = (i & 31) << 2;
      *(float4*)&Bs[kk][nq] = cvt4(*(const float4*)(W + (size_t)(k0 + kk) * N_ + n0 + nq));
    }
    __syncthreads();
    #pragma unroll
    for (int ks = 0; ks < 32; ks += 8) {
      uint32_t af[2][4];
      #pragma unroll
      for (int mt = 0; mt < 2; mt++) {
        int r = wm * 32 + mt * 16 + g4;
        af[mt][0] = __float_as_uint(As[r][ks + tq]);
        af[mt][1] = __float_as_uint(As[r + 8][ks + tq]);
        af[mt][2] = __float_as_uint(As[r][ks + tq + 4]);
        af[mt][3] = __float_as_uint(As[r + 8][ks + tq + 4]);
      }
      #pragma unroll
      for (int nt = 0; nt < 4; nt++) {
        int ccol = wn * 32 + nt * 8 + g4;
        uint32_t b0 = __float_as_uint(Bs[ks + tq][ccol]);
        uint32_t b1 = __float_as_uint(Bs[ks + tq + 4][ccol]);
        #pragma unroll
        for (int mt = 0; mt < 2; mt++)
          mma8(acc[mt][nt], af[mt][0], af[mt][1], af[mt][2], af[mt][3], b0, b1);
      }
    }
    __syncthreads();
  }
  size_t gb = (size_t)(dg * T_ + t) * (N_ * B_);
  #pragma unroll
  for (int mt = 0; mt < 2; mt++) {
    int brow = wm * 32 + mt * 16 + g4;
    #pragma unroll
    for (int nt = 0; nt < 4; nt++) {
      int nc = n0 + wn * 32 + nt * 8 + 2 * tq;
      *(float2*)&g_G[gb + (size_t)brow * N_ + nc] =
          make_float2(acc[mt][nt][0], acc[mt][nt][1]);
      *(float2*)&g_G[gb + (size_t)(brow + 8) * N_ + nc] =
          make_float2(acc[mt][nt][2], acc[mt][nt][3]);
    }
  }
}

// ---------------- Phase 2: persistent recurrent kernel ---------------------
// 512 thr. Warp (ch, kq): ALL 4 gates x 16 n-rows (4 m16 A-tiles), b-cols
// [ch*32, +32) (nt=4), k-slice [kq*128, +128) in 4 chunks of 32.
// Pair kq (warps 2kq, 2kq+1) shares a private staged double buffer.
#define BUFW 2560                  // 64 b * 40 words per chunk buffer
#define PAIRW 5120                 // 2 buffers per pair
#define SMEM_BYTES (8 * PAIRW * 4) // 163840
// zs overlaid on each pair's own region after drain: [r 64][cl 66]
#define ZS(q, r, cl) ((q) * PAIRW + (r) * 66 + (cl))

__global__ void __launch_bounds__(512) k_recur(PU pu, float* __restrict__ out) {
  extern __shared__ float sm[];
  uint32_t smb = (uint32_t)__cvta_generic_to_shared(sm);
  int tid = threadIdx.x, wid = tid >> 5, lane = tid & 31;
  int g4 = lane >> 2, tq = lane & 3;
  int dir = blockIdx.x >> 6, tile = blockIdx.x & 63, rn = tile << 4;
  int ch = wid & 1, kq = wid >> 1;
  int pt = ch * 32 + lane;                 // pair-local tid 0..63
  int barid = 1 + kq;

  const uint4* upk = g_Upk + ((((size_t)dir * 64 + tile) * 8 + kq) << 11) + lane;
  uint32_t pair_smb = smb + kq * PAIRW * 4;

  // elementwise ownership: b = tid>>3, n = rn + nn, nn+1
  int b_e = tid >> 3;
  int nn = (tid & 7) << 1;

  float bia[4][2];
  #pragma unroll
  for (int g = 0; g < 4; g++) {
    bia[g][0] = pu.bia[dir * 4 + g][rn + nn];
    bia[g][1] = pu.bia[dir * 4 + g][rn + nn + 1];
  }
  const float* Gb0 = g_G + (size_t)(dir * 3 + 0) * T_ * N_ * B_;
  const float* Gb1 = g_G + (size_t)(dir * 3 + 1) * T_ * N_ * B_;
  const float* Gb2 = g_G + (size_t)(dir * 3 + 2) * T_ * N_ * B_;
  int hslot0 = kperm(rn + nn), hslot1 = kperm(rn + nn + 1);
  unsigned* barp = &g_bar[dir * T_];
  volatile unsigned* myflag = &g_flag[dir][tile][0];

  float creg[2] = {0.f, 0.f};

  for (int s = 0; s < T_; ++s) {
    const float* hsrc = g_hP[s & 1][dir];
    const float* hkq = hsrc + kq * 128;

    // stage chunks 0,1 into bufs 0,1 (pair-private)
    #pragma unroll
    for (int c0 = 0; c0 < 2; c0++) {
      #pragma unroll
      for (int j = 0; j < 8; j++) {
        int unit = pt + j * 64;
        int b = unit >> 3, seg = unit & 7;
        cpa16(pair_smb + (c0 * BUFW + b * 40 + seg * 4) * 4,
              hkq + b * N_ + c0 * 32 + seg * 4);
      }
      asm volatile("cp.async.commit_group;");
    }

    // prefetch this step's G (coalesced float2, [t][b][n] layout)
    size_t goff = ((size_t)s * B_ + b_e) * N_ + rn + nn;
    float2 gq0 = __ldg((const float2*)(Gb0 + goff));
    float2 gq1 = __ldg((const float2*)(Gb1 + goff));
    float2 gq2 = __ldg((const float2*)(Gb2 + goff));

    float acc[4][4][4];
    #pragma unroll
    for (int at = 0; at < 4; at++)
      #pragma unroll
      for (int nt = 0; nt < 4; nt++)
        #pragma unroll
        for (int cc = 0; cc < 4; cc++) acc[at][nt][cc] = 0.f;

    // 4 chunks x 4 k-steps; 4 A-tiles (gates) x 4 nt per k-step
    #pragma unroll 1
    for (int c = 0; c < 4; ++c) {
      if (c < 3) asm volatile("cp.async.wait_group 1;");
      else       asm volatile("cp.async.wait_group 0;");
      barp64(barid);                // chunk c visible to both warps

      const float* bb = sm + kq * PAIRW + (c & 1) * BUFW + 2 * tq;
      const uint4* up = upk + c * 512;     // 4 ksteps * 128 uint4
      #pragma unroll
      for (int ks = 0; ks < 4; ++ks) {
        uint4 A0 = __ldg(up + ks * 128);
        uint4 A1 = __ldg(up + ks * 128 + 32);
        uint4 A2 = __ldg(up + ks * 128 + 64);
        uint4 A3 = __ldg(up + ks * 128 + 96);
        #pragma unroll
        for (int nt = 0; nt < 4; ++nt) {
          uint2 Bv = *(const uint2*)(bb + (ch * 32 + nt * 8 + g4) * 40 + ks * 8);
          mma8(acc[0][nt], A0.x, A0.y, A0.z, A0.w, Bv.x, Bv.y);
          mma8(acc[1][nt], A1.x, A1.y, A1.z, A1.w, Bv.x, Bv.y);
          mma8(acc[2][nt], A2.x, A2.y, A2.z, A2.w, Bv.x, Bv.y);
          mma8(acc[3][nt], A3.x, A3.y, A3.z, A3.w, Bv.x, Bv.y);
        }
      }
      if (c < 2) {
        barp64(barid);              // both warps done with buf c&1
        int cn = c + 2;
        #pragma unroll
        for (int j = 0; j < 8; j++) {
          int unit = pt + j * 64;
          int b = unit >> 3, seg = unit & 7;
          cpa16(pair_smb + ((c & 1) * BUFW + b * 40 + seg * 4) * 4,
                hkq + b * N_ + cn * 32 + seg * 4);
        }
        asm volatile("cp.async.commit_group;");
      }
    }

    barp64(barid);   // partner drained buf1 -> pair region reusable as zs

    // write k-partials into own pair region: zs[kq][gate*16 + nloc][b]
    #pragma unroll
    for (int at = 0; at < 4; at++) {
      int r = at * 16 + g4;
      #pragma unroll
      for (int nt = 0; nt < 4; nt++) {
        int cl = ch * 32 + nt * 8 + 2 * tq;
        *(float2*)&sm[ZS(kq, r, cl)] =
            make_float2(acc[at][nt][0], acc[at][nt][1]);
        *(float2*)&sm[ZS(kq, r + 8, cl)] =
            make_float2(acc[at][nt][2], acc[at][nt][3]);
      }
    }
    __syncthreads();

    // elementwise LSTM cell (2 consecutive n per thread, one b)
    float z[4][2];
    #pragma unroll
    for (int g = 0; g < 4; g++) {
      #pragma unroll
      for (int e = 0; e < 2; e++) {
        float zz = bia[g][e];
        #pragma unroll
        for (int q = 0; q < 8; q++) zz += sm[ZS(q, g * 16 + nn + e, b_e)];
        z[g][e] = zz;
      }
    }
    float* hdst = g_hP[(s + 1) & 1][dir];
    int t_out = dir ? (T_ - 1 - s) : s;
    float2 ho;
    #pragma unroll
    for (int e = 0; e < 2; e++) {
      float gf = e ? gq0.y : gq0.x;
      float gi = e ? gq1.y : gq1.x;
      float gc = e ? gq2.y : gq2.x;
      float zf = z[0][e] + gf, zi = z[1][e] + gi;
      float zc = z[2][e] + gc, zo = z[3][e] + gf;   // o reuses gf (ref bug)
      float f  = sigm_f(zf);
      float ig = sigm_f(zi);
      float o  = sigm_f(zo);
      float cn = f * creg[e] + ig * tanh_f(zc);
      creg[e] = cn;
      float hh = o * tanh_f(cn);
      ((float*)&ho)[e] = hh;
      __stcg(hdst + b_e * N_ + (e ? hslot1 : hslot0), __uint_as_float(f2tf(hh)));
    }
    *(float2*)(out + ((size_t)t_out * B_ + b_e) * (2 * N_) +
               (size_t)dir * N_ + rn + nn) = ho;

    // per-direction grid barrier: count + broadcast flags (no shared-line spin)
    if (s < T_ - 1) {
      __syncthreads();     // all h-stores happen-before tid0's release-atomic
      if (tid == 0) {
        unsigned v;
        asm volatile("atom.add.acq_rel.gpu.global.u32 %0, [%1], 1;"
                     : "=r"(v) : "l"(&barp[s]) : "memory");
        unsigned want = (unsigned)(s + 1);
        if (v + 1u == NBD) {
          asm volatile("fence.release.gpu;" ::: "memory");
          #pragma unroll 4
          for (int j = 0; j < NBD; j++) {
            asm volatile("st.relaxed.gpu.global.u32 [%0], %1;"
                         :: "l"(&g_flag[dir][j][0]), "r"(want) : "memory");
          }
        } else {
          unsigned w;
          do {
            asm volatile("ld.acquire.gpu.global.u32 %0, [%1];"
                         : "=r"(w) : "l"((const unsigned*)myflag) : "memory");
            if (w >= want) break;
            __nanosleep(32);
          } while (true);
        }
      }
      __syncthreads();     // acquire ordering propagates block-wide
    }
  }
}

extern "C" void kernel_launch(void* const* d_in, const int* in_sizes, int n_in,
                              void* d_out, int out_size) {
  const float* x      = (const float*)d_in[0];
  const float* hidden = (const float*)d_in[1];
  PW pw;
  pw.p[0] = (const float*)d_in[2];   // Wf1
  pw.p[1] = (const float*)d_in[3];   // Wi1
  pw.p[2] = (const float*)d_in[4];   // Wc1
  pw.p[3] = (const float*)d_in[13];  // Wf2
  pw.p[4] = (const float*)d_in[14];  // Wi2
  pw.p[5] = (const float*)d_in[15];  // Wc2

  PU pu;  // gate order f,i,c,o
  pu.U[0] = (const float*)d_in[5];   // Uf1
  pu.U[1] = (const float*)d_in[6];   // Ui1
  pu.U[2] = (const float*)d_in[8];   // Uc1
  pu.U[3] = (const float*)d_in[7];   // Uo1
  pu.U[4] = (const float*)d_in[16];  // Uf2
  pu.U[5] = (const float*)d_in[17];  // Ui2
  pu.U[6] = (const float*)d_in[19];  // Uc2
  pu.U[7] = (const float*)d_in[18];  // Uo2
  pu.bia[0] = (const float*)d_in[9];   // bf1
  pu.bia[1] = (const float*)d_in[10];  // bi1
  pu.bia[2] = (const float*)d_in[12];  // bc1
  pu.bia[3] = (const float*)d_in[11];  // bo1
  pu.bia[4] = (const float*)d_in[20];  // bf2
  pu.bia[5] = (const float*)d_in[21];  // bi2
  pu.bia[6] = (const float*)d_in[23];  // bc2
  pu.bia[7] = (const float*)d_in[22];  // bo2

  static int smem_set = 0;
  if (!smem_set) {
    cudaFuncSetAttribute(k_recur, cudaFuncAttributeMaxDynamicSharedMemorySize,
                         SMEM_BYTES);
    smem_set = 1;
  }

  k_init<<<256, 256>>>(hidden);
  k_pack<<<8192, 256>>>(pu);
  k_gemm_xw<<<dim3(8, 256, 6), 256>>>(x, pw);
  k_recur<<<NB_REC, 512, SMEM_BYTES>>>(pu, (float*)d_out);
}

// round 13
// speedup vs baseline: 1.1877x; 1.0457x over previous
#include <cuda_runtime.h>
#include <cstdint>

#define T_ 256
#define B_ 64
#define M_ 512
#define N_ 1024
#define NB_REC 128

// Scratch: G[dir*3+gate][t][b][n]  (gate order f,i,c)
__device__ float g_G[(size_t)6 * T_ * N_ * B_];
// h double buffer, k-pair-permuted + tf32-rounded: [buf][dir][b][kslot 1024]
__device__ float g_hP[2][2][B_ * N_];
// U packed in mma-fragment order as tf32 bit patterns:
// [dir][tile 64][kq 8][c 4][ks 4][gate 4][lane 32] uint4
__device__ uint4 g_Upk[1u << 21];
// per-block monotonic completion flags (128B apart): g_done[dir][tile][0]
// value = latest h step index published by that block
__device__ unsigned g_done[2][64][32];

struct PW { const float* p[6]; };
struct PU { const float* U[8]; const float* bia[8]; };

__device__ __forceinline__ uint32_t f2tf(float v) {
  uint32_t u; asm("cvt.rna.tf32.f32 %0, %1;" : "=r"(u) : "f"(v)); return u;
}
__device__ __forceinline__ void mma8(float* c, uint32_t a0, uint32_t a1,
                                     uint32_t a2, uint32_t a3,
                                     uint32_t b0, uint32_t b1) {
  asm volatile(
    "mma.sync.aligned.m16n8k8.row.col.f32.tf32.tf32.f32 "
    "{%0,%1,%2,%3},{%4,%5,%6,%7},{%8,%9},{%0,%1,%2,%3};\n"
    : "+f"(c[0]), "+f"(c[1]), "+f"(c[2]), "+f"(c[3])
    : "r"(a0), "r"(a1), "r"(a2), "r"(a3), "r"(b0), "r"(b1));
}
__device__ __forceinline__ void cpa16(uint32_t d, const void* s) {
  asm volatile("cp.async.cg.shared.global [%0], [%1], 16;" :: "r"(d), "l"(s));
}
__device__ __forceinline__ void barp64(int id) {
  asm volatile("bar.sync %0, 64;" :: "r"(id) : "memory");
}
__device__ __forceinline__ int kperm(int n) {        // pair (k, k+4) adjacent
  return (n & ~7) + ((n & 3) << 1) + ((n >> 2) & 1);
}
__device__ __forceinline__ float sigm_f(float x) {
  return __fdividef(1.f, 1.f + __expf(-x));
}
__device__ __forceinline__ float tanh_f(float x) {
  return 1.f - __fdividef(2.f, __expf(2.f * x) + 1.f);
}
__device__ __forceinline__ void waitf(const unsigned* p, unsigned want) {
  unsigned w;
  while (true) {
    asm volatile("ld.acquire.gpu.global.u32 %0, [%1];"
                 : "=r"(w) : "l"(p) : "memory");
    if (w >= want) break;
    __nanosleep(20);
  }
}

__global__ void k_init(const float* __restrict__ hidden) {
  int i = blockIdx.x * blockDim.x + threadIdx.x;   // 65536 threads
  if (i < B_ * N_) {
    int b = i >> 10, n = i & 1023;
    float v = __uint_as_float(f2tf(hidden[i]));
    g_hP[0][0][b * N_ + kperm(n)] = v;
    g_hP[0][1][b * N_ + kperm(n)] = v;
  }
  if (i < 128) g_done[i >> 6][i & 63][0] = 0;
}

// Pack U into fragment order (one uint4 per thread).
__global__ void __launch_bounds__(256) k_pack(PU pu) {
  unsigned i = blockIdx.x * 256 + threadIdx.x;
  unsigned lane = i & 31, g = (i >> 5) & 3, ks = (i >> 7) & 3,
           c = (i >> 9) & 3, kq = (i >> 11) & 7, tile = (i >> 14) & 63,
           dir = (i >> 20) & 1;
  int g4 = lane >> 2, tq = lane & 3;
  int row = tile * 16 + g4;
  int k = kq * 128 + c * 32 + ks * 8 + tq;
  const float* U = pu.U[dir * 4 + g];
  uint4 o;
  o.x = f2tf(U[(size_t)row * N_ + k]);
  o.y = f2tf(U[(size_t)(row + 8) * N_ + k]);
  o.z = f2tf(U[(size_t)row * N_ + k + 4]);
  o.w = f2tf(U[(size_t)(row + 8) * N_ + k + 4]);
  g_Upk[i] = o;
}

// ---------------- Phase 1: G[dg][t][b][n] = sum_m x[t_src,b,m] * W[m,n] ----
__device__ __forceinline__ float4 cvt4(float4 v) {
  float4 r;
  r.x = __uint_as_float(f2tf(v.x)); r.y = __uint_as_float(f2tf(v.y));
  r.z = __uint_as_float(f2tf(v.z)); r.w = __uint_as_float(f2tf(v.w));
  return r;
}

__global__ void __launch_bounds__(256) k_gemm_xw(const float* __restrict__ x, PW pw) {
  __shared__ __align__(16) float As[64][36];
  __shared__ __align__(16) float Bs[32][136];
  int tid = threadIdx.x;
  int wid = tid >> 5, lane = tid & 31;
  int g4 = lane >> 2, tq = lane & 3;
  int wm = wid & 1, wn = wid >> 1;
  int n0 = blockIdx.x * 128;
  int t = blockIdx.y;
  int dg = blockIdx.z;
  int dir = dg / 3;
  int t_src = dir ? (T_ - 1 - t) : t;
  const float* W = pw.p[dg];
  const float* xt = x + (size_t)t_src * (B_ * M_);

  float acc[2][4][4];
  #pragma unroll
  for (int a = 0; a < 2; a++)
    #pragma unroll
    for (int b = 0; b < 4; b++)
      #pragma unroll
      for (int cc = 0; cc < 4; cc++) acc[a][b][cc] = 0.f;

  for (int k0 = 0; k0 < M_; k0 += 32) {
    #pragma unroll
    for (int j = 0; j < 2; j++) {
      int i = tid + j * 256;
      int bb = i >> 3, kq = (i & 7) << 2;
      *(float4*)&As[bb][kq] = cvt4(*(const float4*)(xt + bb * M_ + k0 + kq));
    }
    #pragma unroll
    for (int j = 0; j < 4; j++) {
      int i = tid + j * 256;
      int kk = i >> 5, nq = (i & 31) << 2;
      *(float4*)&Bs[kk][nq] = cvt4(*(const float4*)(W + (size_t)(k0 + kk) * N_ + n0 + nq));
    }
    __syncthreads();
    #pragma unroll
    for (int ks = 0; ks < 32; ks += 8) {
      uint32_t af[2][4];
      #pragma unroll
      for (int mt = 0; mt < 2; mt++) {
        int r = wm * 32 + mt * 16 + g4;
        af[mt][0] = __float_as_uint(As[r][ks + tq]);
        af[mt][1] = __float_as_uint(As[r + 8][ks + tq]);
        af[mt][2] = __float_as_uint(As[r][ks + tq + 4]);
        af[mt][3] = __float_as_uint(As[r + 8][ks + tq + 4]);
      }
      #pragma unroll
      for (int nt = 0; nt < 4; nt++) {
        int ccol = wn * 32 + nt * 8 + g4;
        uint32_t b0 = __float_as_uint(Bs[ks + tq][ccol]);
        uint32_t b1 = __float_as_uint(Bs[ks + tq + 4][ccol]);
        #pragma unroll
        for (int mt = 0; mt < 2; mt++)
          mma8(acc[mt][nt], af[mt][0], af[mt][1], af[mt][2], af[mt][3], b0, b1);
      }
    }
    __syncthreads();
  }
  size_t gb = (size_t)(dg * T_ + t) * (N_ * B_);
  #pragma unroll
  for (int mt = 0; mt < 2; mt++) {
    int brow = wm * 32 + mt * 16 + g4;
    #pragma unroll
    for (int nt = 0; nt < 4; nt++) {
      int nc = n0 + wn * 32 + nt * 8 + 2 * tq;
      *(float2*)&g_G[gb + (size_t)brow * N_ + nc] =
          make_float2(acc[mt][nt][0], acc[mt][nt][1]);
      *(float2*)&g_G[gb + (size_t)(brow + 8) * N_ + nc] =
          make_float2(acc[mt][nt][2], acc[mt][nt][3]);
    }
  }
}

// ---------------- Phase 2: persistent recurrent kernel ---------------------
// R9 skeleton: 512 thr, warp PAIR kq owns k-slice [kq*128,+128) staged in a
// pair-private double buffer; warp rg handles gates {2rg,2rg+1}.
// NEW: no grid barrier — per-block dataflow flags. Pair kq chunk c's 32
// k-slots are produced by blocks j = kq*8+2c, +1; pt==0 acquire-polls them.
#define BUFW 2560                  // 64 b * 40 words per chunk buffer
#define PAIRW 5120                 // 2 buffers per pair
#define SMEM_BYTES (8 * PAIRW * 4) // 163840
// zs overlaid on each pair's own region after drain: [r 64][cl 66]
#define ZS(q, r, cl) ((q) * PAIRW + (r) * 66 + (cl))

__global__ void __launch_bounds__(512) k_recur(PU pu, float* __restrict__ out) {
  extern __shared__ float sm[];
  uint32_t smb = (uint32_t)__cvta_generic_to_shared(sm);
  int tid = threadIdx.x, wid = tid >> 5, lane = tid & 31;
  int g4 = lane >> 2, tq = lane & 3;
  int dir = blockIdx.x >> 6, tile = blockIdx.x & 63, rn = tile << 4;
  int rg = wid & 1, kq = wid >> 1;
  int pt = rg * 32 + lane;                 // pair-local tid 0..63
  int barid = 1 + kq;

  const uint4* upk = g_Upk + (((size_t)dir * 64 + tile) << 14)
                     + kq * 2048 + 2 * rg * 32 + lane;
  uint32_t pair_smb = smb + kq * PAIRW * 4;

  // elementwise ownership: b = tid>>3, n = rn + nn, nn+1
  int b_e = tid >> 3;
  int nn = (tid & 7) << 1;

  float bia[4][2];
  #pragma unroll
  for (int g = 0; g < 4; g++) {
    bia[g][0] = pu.bia[dir * 4 + g][rn + nn];
    bia[g][1] = pu.bia[dir * 4 + g][rn + nn + 1];
  }
  const float* Gb0 = g_G + (size_t)(dir * 3 + 0) * T_ * N_ * B_;
  const float* Gb1 = g_G + (size_t)(dir * 3 + 1) * T_ * N_ * B_;
  const float* Gb2 = g_G + (size_t)(dir * 3 + 2) * T_ * N_ * B_;
  int hslot0 = kperm(rn + nn), hslot1 = kperm(rn + nn + 1);

  float creg[2] = {0.f, 0.f};

  // U pipeline: A0/A1 always hold the uint4s for the upcoming k-step.
  uint4 A0 = __ldg(upk), A1 = __ldg(upk + 32);

  for (int s = 0; s < T_; ++s) {
    const float* hsrc = g_hP[s & 1][dir];
    const float* hkq = hsrc + kq * 128;

    // wait for producers of chunks 0,1 (blocks kq*8 .. kq*8+3), then stage
    if (pt == 0) {
      #pragma unroll
      for (int j = 0; j < 4; j++)
        waitf(&g_done[dir][kq * 8 + j][0], (unsigned)s);
    }
    barp64(barid);
    #pragma unroll
    for (int c0 = 0; c0 < 2; c0++) {
      #pragma unroll
      for (int j = 0; j < 8; j++) {
        int unit = pt + j * 64;
        int b = unit >> 3, seg = unit & 7;
        cpa16(pair_smb + (c0 * BUFW + b * 40 + seg * 4) * 4,
              hkq + b * N_ + c0 * 32 + seg * 4);
      }
      asm volatile("cp.async.commit_group;");
    }

    // prefetch this step's G (coalesced float2, [t][b][n] layout)
    size_t goff = ((size_t)s * B_ + b_e) * N_ + rn + nn;
    float2 gq0 = __ldg((const float2*)(Gb0 + goff));
    float2 gq1 = __ldg((const float2*)(Gb1 + goff));
    float2 gq2 = __ldg((const float2*)(Gb2 + goff));

    float acc[2][8][4];
    #pragma unroll
    for (int m = 0; m < 2; m++)
      #pragma unroll
      for (int nt = 0; nt < 8; nt++)
        #pragma unroll
        for (int cc = 0; cc < 4; cc++) acc[m][nt][cc] = 0.f;

    // flattened 16 k-steps (4 chunks x 4), U pipelined one k-step ahead
    #pragma unroll
    for (int t = 0; t < 16; ++t) {
      int c = t >> 2;
      if ((t & 3) == 0) {
        if (c < 3) asm volatile("cp.async.wait_group 1;");
        else       asm volatile("cp.async.wait_group 0;");
        barp64(barid);                   // chunk c visible to both warps
      }
      int tn = (t + 1) & 15;             // t=15 wraps to next step's t=0
      const uint4* upn = upk + ((tn >> 2) * 512 + (tn & 3) * 128);
      uint4 An0 = __ldg(upn), An1 = __ldg(upn + 32);

      const float* bb = sm + kq * PAIRW + ((t >> 2) & 1) * BUFW
                        + (t & 3) * 8 + 2 * tq;
      #pragma unroll
      for (int nt = 0; nt < 8; ++nt) {
        uint2 Bv = *(const uint2*)(bb + (nt * 8 + g4) * 40);
        mma8(acc[0][nt], A0.x, A0.y, A0.z, A0.w, Bv.x, Bv.y);
        mma8(acc[1][nt], A1.x, A1.y, A1.z, A1.w, Bv.x, Bv.y);
      }
      A0 = An0; A1 = An1;

      if ((t & 3) == 3 && c < 2) {
        int cn = c + 2;
        if (pt == 0) {                   // wait for chunk cn's 2 producers
          waitf(&g_done[dir][kq * 8 + 2 * cn][0], (unsigned)s);
          waitf(&g_done[dir][kq * 8 + 2 * cn + 1][0], (unsigned)s);
        }
        barp64(barid);                   // buf c&1 free + flags confirmed
        #pragma unroll
        for (int j = 0; j < 8; j++) {
          int unit = pt + j * 64;
          int b = unit >> 3, seg = unit & 7;
          cpa16(pair_smb + ((c & 1) * BUFW + b * 40 + seg * 4) * 4,
                hkq + b * N_ + cn * 32 + seg * 4);
        }
        asm volatile("cp.async.commit_group;");
      }
    }

    barp64(barid);   // partner done with buf1 -> pair region reusable as zs

    // write k-partials into OWN pair region: zs[kq][gate*16+n][b]
    #pragma unroll
    for (int m = 0; m < 2; m++) {
      int gate = 2 * rg + m;
      #pragma unroll
      for (int nt = 0; nt < 8; nt++) {
        int cl = nt * 8 + 2 * tq;
        *(float2*)&sm[ZS(kq, gate * 16 + g4, cl)] =
            make_float2(acc[m][nt][0], acc[m][nt][1]);
        *(float2*)&sm[ZS(kq, gate * 16 + g4 + 8, cl)] =
            make_float2(acc[m][nt][2], acc[m][nt][3]);
      }
    }
    __syncthreads();

    // elementwise LSTM cell (2 consecutive n per thread, one b)
    float z[4][2];
    #pragma unroll
    for (int g = 0; g < 4; g++) {
      #pragma unroll
      for (int e = 0; e < 2; e++) {
        float zz = bia[g][e];
        #pragma unroll
        for (int q = 0; q < 8; q++) zz += sm[ZS(q, g * 16 + nn + e, b_e)];
        z[g][e] = zz;
      }
    }
    float* hdst = g_hP[(s + 1) & 1][dir];
    int t_out = dir ? (T_ - 1 - s) : s;
    float2 ho;
    #pragma unroll
    for (int e = 0; e < 2; e++) {
      float gf = e ? gq0.y : gq0.x;
      float gi = e ? gq1.y : gq1.x;
      float gc = e ? gq2.y : gq2.x;
      float zf = z[0][e] + gf, zi = z[1][e] + gi;
      float zc = z[2][e] + gc, zo = z[3][e] + gf;   // o reuses gf (ref bug)
      float f  = sigm_f(zf);
      float ig = sigm_f(zi);
      float o  = sigm_f(zo);
      float cn = f * creg[e] + ig * tanh_f(zc);
      creg[e] = cn;
      float h = o * tanh_f(cn);
      ((float*)&ho)[e] = h;
      __stcg(hdst + b_e * N_ + (e ? hslot1 : hslot0), __uint_as_float(f2tf(h)));
    }
    *(float2*)(out + ((size_t)t_out * B_ + b_e) * (2 * N_) +
               (size_t)dir * N_ + rn + nn) = ho;

    // publish: h for step s+1 is written; zs reads done -> buffers reusable
    __syncthreads();
    if (s < T_ - 1 && tid == 0) {
      asm volatile("fence.release.gpu;" ::: "memory");
      asm volatile("st.relaxed.gpu.global.u32 [%0], %1;"
                   :: "l"(&g_done[dir][tile][0]), "r"((unsigned)(s + 1))
                   : "memory");
    }
  }
}

extern "C" void kernel_launch(void* const* d_in, const int* in_sizes, int n_in,
                              void* d_out, int out_size) {
  const float* x      = (const float*)d_in[0];
  const float* hidden = (const float*)d_in[1];
  PW pw;
  pw.p[0] = (const float*)d_in[2];   // Wf1
  pw.p[1] = (const float*)d_in[3];   // Wi1
  pw.p[2] = (const float*)d_in[4];   // Wc1
  pw.p[3] = (const float*)d_in[13];  // Wf2
  pw.p[4] = (const float*)d_in[14];  // Wi2
  pw.p[5] = (const float*)d_in[15];  // Wc2

  PU pu;  // gate order f,i,c,o
  pu.U[0] = (const float*)d_in[5];   // Uf1
  pu.U[1] = (const float*)d_in[6];   // Ui1
  pu.U[2] = (const float*)d_in[8];   // Uc1
  pu.U[3] = (const float*)d_in[7];   // Uo1
  pu.U[4] = (const float*)d_in[16];  // Uf2
  pu.U[5] = (const float*)d_in[17];  // Ui2
  pu.U[6] = (const float*)d_in[19];  // Uc2
  pu.U[7] = (const float*)d_in[18];  // Uo2
  pu.bia[0] = (const float*)d_in[9];   // bf1
  pu.bia[1] = (const float*)d_in[10];  // bi1
  pu.bia[2] = (const float*)d_in[12];  // bc1
  pu.bia[3] = (const float*)d_in[11];  // bo1
  pu.bia[4] = (const float*)d_in[20];  // bf2
  pu.bia[5] = (const float*)d_in[21];  // bi2
  pu.bia[6] = (const float*)d_in[23];  // bc2
  pu.bia[7] = (const float*)d_in[22];  // bo2

  static int smem_set = 0;
  if (!smem_set) {
    cudaFuncSetAttribute(k_recur, cudaFuncAttributeMaxDynamicSharedMemorySize,
                         SMEM_BYTES);
    smem_set = 1;
  }

  k_init<<<256, 256>>>(hidden);
  k_pack<<<8192, 256>>>(pu);
  k_gemm_xw<<<dim3(8, 256, 6), 256>>>(x, pw);
  k_recur<<<NB_REC, 512, SMEM_BYTES>>>(pu, (float*)d_out);
}

// round 16
// speedup vs baseline: 1.2780x; 1.0760x over previous
#include <cuda_runtime.h>
#include <cstdint>

#define T_ 256
#define B_ 64
#define M_ 512
#define N_ 1024
#define NB_REC 128
#define NBD 64          // blocks per direction (barrier arrivals)

// Scratch: G[dir*3+gate][t][b][n]  (gate order f,i,c)
__device__ float g_G[(size_t)6 * T_ * N_ * B_];
// h double buffer, k-pair-permuted + tf32-rounded: [buf][dir][b][kslot 1024]
__device__ float g_hP[2][2][B_ * N_];
// U packed in mma-fragment order as tf32 bit patterns:
// [dir][tile 64][kq 8][c 4][ks 4][gate 4][lane 32] uint4
__device__ uint4 g_Upk[1u << 21];
// per-step per-dir grid barrier counters (zeroed by k_init every launch)
__device__ unsigned g_bar[2 * T_];

struct PW { const float* p[6]; };
struct PU { const float* U[8]; const float* bia[8]; };

__device__ __forceinline__ uint32_t f2tf(float v) {
  uint32_t u; asm("cvt.rna.tf32.f32 %0, %1;" : "=r"(u) : "f"(v)); return u;
}
__device__ __forceinline__ void mma8(float* c, uint32_t a0, uint32_t a1,
                                     uint32_t a2, uint32_t a3,
                                     uint32_t b0, uint32_t b1) {
  asm volatile(
    "mma.sync.aligned.m16n8k8.row.col.f32.tf32.tf32.f32 "
    "{%0,%1,%2,%3},{%4,%5,%6,%7},{%8,%9},{%0,%1,%2,%3};\n"
    : "+f"(c[0]), "+f"(c[1]), "+f"(c[2]), "+f"(c[3])
    : "r"(a0), "r"(a1), "r"(a2), "r"(a3), "r"(b0), "r"(b1));
}
__device__ __forceinline__ void cpa16(uint32_t d, const void* s) {
  asm volatile("cp.async.cg.shared.global [%0], [%1], 16;" :: "r"(d), "l"(s));
}
__device__ __forceinline__ void barp64(int id) {
  asm volatile("bar.sync %0, 64;" :: "r"(id) : "memory");
}
__device__ __forceinline__ int kperm(int n) {        // pair (k, k+4) adjacent
  return (n & ~7) + ((n & 3) << 1) + ((n >> 2) & 1);
}
__device__ __forceinline__ float sigm_f(float x) {
  return __fdividef(1.f, 1.f + __expf(-x));
}
__device__ __forceinline__ float tanh_f(float x) {
  return 1.f - __fdividef(2.f, __expf(2.f * x) + 1.f);
}

__global__ void k_init(const float* __restrict__ hidden) {
  int i = blockIdx.x * blockDim.x + threadIdx.x;   // 65536 threads
  if (i < B_ * N_) {
    int b = i >> 10, n = i & 1023;
    float v = __uint_as_float(f2tf(hidden[i]));
    g_hP[0][0][b * N_ + kperm(n)] = v;
    g_hP[0][1][b * N_ + kperm(n)] = v;
  }
  if (i < 2 * T_) g_bar[i] = 0;
}

// Pack U into fragment order (one uint4 per thread).
__global__ void __launch_bounds__(256) k_pack(PU pu) {
  unsigned i = blockIdx.x * 256 + threadIdx.x;
  unsigned lane = i & 31, g = (i >> 5) & 3, ks = (i >> 7) & 3,
           c = (i >> 9) & 3, kq = (i >> 11) & 7, tile = (i >> 14) & 63,
           dir = (i >> 20) & 1;
  int g4 = lane >> 2, tq = lane & 3;
  int row = tile * 16 + g4;
  int k = kq * 128 + c * 32 + ks * 8 + tq;
  const float* U = pu.U[dir * 4 + g];
  uint4 o;
  o.x = f2tf(U[(size_t)row * N_ + k]);
  o.y = f2tf(U[(size_t)(row + 8) * N_ + k]);
  o.z = f2tf(U[(size_t)row * N_ + k + 4]);
  o.w = f2tf(U[(size_t)(row + 8) * N_ + k + 4]);
  g_Upk[i] = o;
}

// ---------------- Phase 1: G[dg][t][b][n] = sum_m x[t_src,b,m] * W[m,n] ----
// cp.async double-buffered pipeline; fp32 in smem, cvt.rna in fragment build.
// dyn smem layout (floats): A[2][64][36] at 0 (stride 2304), B[2][32][136]
// at 4608 (stride 4352). total 13312 floats = 53248 B.
#define GA_STR 2304
#define GB_OFF 4608
#define GB_STR 4352
#define GSM_BYTES 53248

__global__ void __launch_bounds__(256) k_gemm_xw(const float* __restrict__ x, PW pw) {
  extern __shared__ float gsm[];
  uint32_t smb = (uint32_t)__cvta_generic_to_shared(gsm);
  int tid = threadIdx.x;
  int wid = tid >> 5, lane = tid & 31;
  int g4 = lane >> 2, tq = lane & 3;
  int wm = wid & 1, wn = wid >> 1;
  int n0 = blockIdx.x * 128;
  int t = blockIdx.y;
  int dg = blockIdx.z;
  int dir = dg / 3;
  int t_src = dir ? (T_ - 1 - t) : t;
  const float* W = pw.p[dg];
  const float* xt = x + (size_t)t_src * (B_ * M_);

  // issue chunk c into buffer buf
  auto issue = [&](int c, int buf) {
    #pragma unroll
    for (int j = 0; j < 2; j++) {            // A: 64 x 32
      int unit = tid + j * 256;
      int row = unit >> 3, f4 = (unit & 7) << 2;
      cpa16(smb + (buf * GA_STR + row * 36 + f4) * 4,
            xt + row * M_ + c * 32 + f4);
    }
    #pragma unroll
    for (int j = 0; j < 4; j++) {            // B: 32 x 128
      int unit = tid + j * 256;
      int kr = unit >> 5, f4 = (unit & 31) << 2;
      cpa16(smb + (GB_OFF + buf * GB_STR + kr * 136 + f4) * 4,
            W + (size_t)(c * 32 + kr) * N_ + n0 + f4);
    }
    asm volatile("cp.async.commit_group;");
  };

  float acc[2][4][4];
  #pragma unroll
  for (int a = 0; a < 2; a++)
    #pragma unroll
    for (int b = 0; b < 4; b++)
      #pragma unroll
      for (int cc = 0; cc < 4; cc++) acc[a][b][cc] = 0.f;

  issue(0, 0);
  #pragma unroll 1
  for (int c = 0; c < 16; ++c) {
    if (c < 15) {
      issue(c + 1, (c + 1) & 1);
      asm volatile("cp.async.wait_group 1;");
    } else {
      asm volatile("cp.async.wait_group 0;");
    }
    __syncthreads();
    const float* As = gsm + (c & 1) * GA_STR;
    const float* Bs = gsm + GB_OFF + (c & 1) * GB_STR;
    #pragma unroll
    for (int ks = 0; ks < 32; ks += 8) {
      uint32_t af[2][4];
      #pragma unroll
      for (int mt = 0; mt < 2; mt++) {
        int r = wm * 32 + mt * 16 + g4;
        af[mt][0] = f2tf(As[r * 36 + ks + tq]);
        af[mt][1] = f2tf(As[(r + 8) * 36 + ks + tq]);
        af[mt][2] = f2tf(As[r * 36 + ks + tq + 4]);
        af[mt][3] = f2tf(As[(r + 8) * 36 + ks + tq + 4]);
      }
      #pragma unroll
      for (int nt = 0; nt < 4; nt++) {
        int ccol = wn * 32 + nt * 8 + g4;
        uint32_t b0 = f2tf(Bs[(ks + tq) * 136 + ccol]);
        uint32_t b1 = f2tf(Bs[(ks + tq + 4) * 136 + ccol]);
        #pragma unroll
        for (int mt = 0; mt < 2; mt++)
          mma8(acc[mt][nt], af[mt][0], af[mt][1], af[mt][2], af[mt][3], b0, b1);
      }
    }
    __syncthreads();
  }
  size_t gb = (size_t)(dg * T_ + t) * (N_ * B_);
  #pragma unroll
  for (int mt = 0; mt < 2; mt++) {
    int brow = wm * 32 + mt * 16 + g4;
    #pragma unroll
    for (int nt = 0; nt < 4; nt++) {
      int nc = n0 + wn * 32 + nt * 8 + 2 * tq;
      *(float2*)&g_G[gb + (size_t)brow * N_ + nc] =
          make_float2(acc[mt][nt][0], acc[mt][nt][1]);
      *(float2*)&g_G[gb + (size_t)(brow + 8) * N_ + nc] =
          make_float2(acc[mt][nt][2], acc[mt][nt][3]);
    }
  }
}

// ---------------- Phase 2: persistent recurrent kernel (exact R9) ----------
#define BUFW 2560                  // 64 * 40 words per chunk buffer
#define PAIRW 5120                 // 2 buffers
#define SMEM_BYTES (8 * PAIRW * 4) // 163840
#define ZS(q, r, cl) ((q) * PAIRW + (r) * 66 + (cl))

__global__ void __launch_bounds__(512) k_recur(PU pu, float* __restrict__ out) {
  extern __shared__ float sm[];
  uint32_t smb = (uint32_t)__cvta_generic_to_shared(sm);
  int tid = threadIdx.x, wid = tid >> 5, lane = tid & 31;
  int g4 = lane >> 2, tq = lane & 3;
  int dir = blockIdx.x >> 6, tile = blockIdx.x & 63, rn = tile << 4;
  int rg = wid & 1, kq = wid >> 1;
  int pt = rg * 32 + lane;                 // pair-local tid 0..63
  int barid = 1 + kq;

  const uint4* upk = g_Upk + (((size_t)dir * 64 + tile) << 14)
                     + kq * 2048 + 2 * rg * 32 + lane;
  uint32_t pair_smb = smb + kq * PAIRW * 4;

  int b_e = tid >> 3;
  int nn = (tid & 7) << 1;

  float bia[4][2];
  #pragma unroll
  for (int g = 0; g < 4; g++) {
    bia[g][0] = pu.bia[dir * 4 + g][rn + nn];
    bia[g][1] = pu.bia[dir * 4 + g][rn + nn + 1];
  }
  const float* Gb0 = g_G + (size_t)(dir * 3 + 0) * T_ * N_ * B_;
  const float* Gb1 = g_G + (size_t)(dir * 3 + 1) * T_ * N_ * B_;
  const float* Gb2 = g_G + (size_t)(dir * 3 + 2) * T_ * N_ * B_;
  int hslot0 = kperm(rn + nn), hslot1 = kperm(rn + nn + 1);
  unsigned* barp = &g_bar[dir * T_];

  float creg[2] = {0.f, 0.f};

  uint4 A0 = __ldg(upk), A1 = __ldg(upk + 32);

  for (int s = 0; s < T_; ++s) {
    const float* hsrc = g_hP[s & 1][dir];
    const float* hkq = hsrc + kq * 128;

    #pragma unroll
    for (int c0 = 0; c0 < 2; c0++) {
      #pragma unroll
      for (int j = 0; j < 8; j++) {
        int unit = pt + j * 64;
        int b = unit >> 3, seg = unit & 7;
        cpa16(pair_smb + (c0 * BUFW + b * 40 + seg * 4) * 4,
              hkq + b * N_ + c0 * 32 + seg * 4);
      }
      asm volatile("cp.async.commit_group;");
    }

    size_t goff = ((size_t)s * B_ + b_e) * N_ + rn + nn;
    float2 gq0 = __ldg((const float2*)(Gb0 + goff));
    float2 gq1 = __ldg((const float2*)(Gb1 + goff));
    float2 gq2 = __ldg((const float2*)(Gb2 + goff));

    float acc[2][8][4];
    #pragma unroll
    for (int m = 0; m < 2; m++)
      #pragma unroll
      for (int nt = 0; nt < 8; nt++)
        #pragma unroll
        for (int cc = 0; cc < 4; cc++) acc[m][nt][cc] = 0.f;

    #pragma unroll
    for (int t = 0; t < 16; ++t) {
      int c = t >> 2;
      if ((t & 3) == 0) {
        if (c < 3) asm volatile("cp.async.wait_group 1;");
        else       asm volatile("cp.async.wait_group 0;");
        barp64(barid);
      }
      int tn = (t + 1) & 15;
      const uint4* upn = upk + ((tn >> 2) * 512 + (tn & 3) * 128);
      uint4 An0 = __ldg(upn), An1 = __ldg(upn + 32);

      const float* bb = sm + kq * PAIRW + ((t >> 2) & 1) * BUFW
                        + (t & 3) * 8 + 2 * tq;
      #pragma unroll
      for (int nt = 0; nt < 8; ++nt) {
        uint2 Bv = *(const uint2*)(bb + (nt * 8 + g4) * 40);
        mma8(acc[0][nt], A0.x, A0.y, A0.z, A0.w, Bv.x, Bv.y);
        mma8(acc[1][nt], A1.x, A1.y, A1.z, A1.w, Bv.x, Bv.y);
      }
      A0 = An0; A1 = An1;

      if ((t & 3) == 3 && c < 2) {
        barp64(barid);
        int cn = c + 2;
        #pragma unroll
        for (int j = 0; j < 8; j++) {
          int unit = pt + j * 64;
          int b = unit >> 3, seg = unit & 7;
          cpa16(pair_smb + ((c & 1) * BUFW + b * 40 + seg * 4) * 4,
                hkq + b * N_ + cn * 32 + seg * 4);
        }
        asm volatile("cp.async.commit_group;");
      }
    }

    barp64(barid);

    #pragma unroll
    for (int m = 0; m < 2; m++) {
      int gate = 2 * rg + m;
      #pragma unroll
      for (int nt = 0; nt < 8; nt++) {
        int cl = nt * 8 + 2 * tq;
        *(float2*)&sm[ZS(kq, gate * 16 + g4, cl)] =
            make_float2(acc[m][nt][0], acc[m][nt][1]);
        *(float2*)&sm[ZS(kq, gate * 16 + g4 + 8, cl)] =
            make_float2(acc[m][nt][2], acc[m][nt][3]);
      }
    }
    __syncthreads();

    float z[4][2];
    #pragma unroll
    for (int g = 0; g < 4; g++) {
      #pragma unroll
      for (int e = 0; e < 2; e++) {
        float zz = bia[g][e];
        #pragma unroll
        for (int q = 0; q < 8; q++) zz += sm[ZS(q, g * 16 + nn + e, b_e)];
        z[g][e] = zz;
      }
    }
    float* hdst = g_hP[(s + 1) & 1][dir];
    int t_out = dir ? (T_ - 1 - s) : s;
    float2 ho;
    #pragma unroll
    for (int e = 0; e < 2; e++) {
      float gf = e ? gq0.y : gq0.x;
      float gi = e ? gq1.y : gq1.x;
      float gc = e ? gq2.y : gq2.x;
      float zf = z[0][e] + gf, zi = z[1][e] + gi;
      float zc = z[2][e] + gc, zo = z[3][e] + gf;   // o reuses gf (ref bug)
      float f  = sigm_f(zf);
      float ig = sigm_f(zi);
      float o  = sigm_f(zo);
      float cn = f * creg[e] + ig * tanh_f(zc);
      creg[e] = cn;
      float h = o * tanh_f(cn);
      ((float*)&ho)[e] = h;
      __stcg(hdst + b_e * N_ + (e ? hslot1 : hslot0), __uint_as_float(f2tf(h)));
    }
    *(float2*)(out + ((size_t)t_out * B_ + b_e) * (2 * N_) +
               (size_t)dir * N_ + rn + nn) = ho;

    if (s < T_ - 1) {
      __syncthreads();
      if (tid == 0) {
        unsigned v;
        asm volatile("atom.add.acq_rel.gpu.global.u32 %0, [%1], 1;"
                     : "=r"(v) : "l"(&barp[s]) : "memory");
        if (v + 1u < NBD) {
          unsigned w;
          do {
            asm volatile("ld.acquire.gpu.global.u32 %0, [%1];"
                         : "=r"(w) : "l"(&barp[s]) : "memory");
            if (w >= NBD) break;
            __nanosleep(32);
          } while (true);
        }
      }
      __syncthreads();
    }
  }
}

extern "C" void kernel_launch(void* const* d_in, const int* in_sizes, int n_in,
                              void* d_out, int out_size) {
  const float* x      = (const float*)d_in[0];
  const float* hidden = (const float*)d_in[1];
  PW pw;
  pw.p[0] = (const float*)d_in[2];   // Wf1
  pw.p[1] = (const float*)d_in[3];   // Wi1
  pw.p[2] = (const float*)d_in[4];   // Wc1
  pw.p[3] = (const float*)d_in[13];  // Wf2
  pw.p[4] = (const float*)d_in[14];  // Wi2
  pw.p[5] = (const float*)d_in[15];  // Wc2

  PU pu;  // gate order f,i,c,o
  pu.U[0] = (const float*)d_in[5];   // Uf1
  pu.U[1] = (const float*)d_in[6];   // Ui1
  pu.U[2] = (const float*)d_in[8];   // Uc1
  pu.U[3] = (const float*)d_in[7];   // Uo1
  pu.U[4] = (const float*)d_in[16];  // Uf2
  pu.U[5] = (const float*)d_in[17];  // Ui2
  pu.U[6] = (const float*)d_in[19];  // Uc2
  pu.U[7] = (const float*)d_in[18];  // Uo2
  pu.bia[0] = (const float*)d_in[9];   // bf1
  pu.bia[1] = (const float*)d_in[10];  // bi1
  pu.bia[2] = (const float*)d_in[12];  // bc1
  pu.bia[3] = (const float*)d_in[11];  // bo1
  pu.bia[4] = (const float*)d_in[20];  // bf2
  pu.bia[5] = (const float*)d_in[21];  // bi2
  pu.bia[6] = (const float*)d_in[23];  // bc2
  pu.bia[7] = (const float*)d_in[22];  // bo2

  static int smem_set = 0;
  if (!smem_set) {
    cudaFuncSetAttribute(k_recur, cudaFuncAttributeMaxDynamicSharedMemorySize,
                         SMEM_BYTES);
    cudaFuncSetAttribute(k_gemm_xw, cudaFuncAttributeMaxDynamicSharedMemorySize,
                         GSM_BYTES);
    smem_set = 1;
  }

  k_init<<<256, 256>>>(hidden);
  k_pack<<<8192, 256>>>(pu);
  k_gemm_xw<<<dim3(8, 256, 6), 256, GSM_BYTES>>>(x, pw);
  k_recur<<<NB_REC, 512, SMEM_BYTES>>>(pu, (float*)d_out);
}

// round 17
// speedup vs baseline: 1.2921x; 1.0110x over previous
#include <cuda_runtime.h>
#include <cstdint>

#define T_ 256
#define B_ 64
#define M_ 512
#define N_ 1024
#define NB_REC 128
#define NBD 64          // blocks per direction (barrier arrivals)

// Scratch: G[dir*3+gate][t][b][n]  (gate order f,i,c)
__device__ float g_G[(size_t)6 * T_ * N_ * B_];
// h double buffer, k-pair-permuted + tf32-rounded: [buf][dir][b][kslot 1024]
__device__ float g_hP[2][2][B_ * N_];
// U packed in mma-fragment order as tf32 bit patterns:
// [dir][tile 64][kq 8][c 4][ks 4][gate 4][lane 32] uint4
__device__ uint4 g_Upk[1u << 21];
// per-step per-dir grid barrier counters (zeroed by k_init every launch)
__device__ unsigned g_bar[2 * T_];

struct PW { const float* p[6]; };
struct PU { const float* U[8]; const float* bia[8]; };

__device__ __forceinline__ uint32_t f2tf(float v) {
  uint32_t u; asm("cvt.rna.tf32.f32 %0, %1;" : "=r"(u) : "f"(v)); return u;
}
__device__ __forceinline__ void mma8(float* c, uint32_t a0, uint32_t a1,
                                     uint32_t a2, uint32_t a3,
                                     uint32_t b0, uint32_t b1) {
  asm volatile(
    "mma.sync.aligned.m16n8k8.row.col.f32.tf32.tf32.f32 "
    "{%0,%1,%2,%3},{%4,%5,%6,%7},{%8,%9},{%0,%1,%2,%3};\n"
    : "+f"(c[0]), "+f"(c[1]), "+f"(c[2]), "+f"(c[3])
    : "r"(a0), "r"(a1), "r"(a2), "r"(a3), "r"(b0), "r"(b1));
}
__device__ __forceinline__ void cpa16(uint32_t d, const void* s) {
  asm volatile("cp.async.cg.shared.global [%0], [%1], 16;" :: "r"(d), "l"(s));
}
__device__ __forceinline__ void barp64(int id) {
  asm volatile("bar.sync %0, 64;" :: "r"(id) : "memory");
}
__device__ __forceinline__ int kperm(int n) {        // pair (k, k+4) adjacent
  return (n & ~7) + ((n & 3) << 1) + ((n >> 2) & 1);
}
__device__ __forceinline__ float sigm_f(float x) {
  return __fdividef(1.f, 1.f + __expf(-x));
}
__device__ __forceinline__ float tanh_f(float x) {
  return 1.f - __fdividef(2.f, __expf(2.f * x) + 1.f);
}

__global__ void k_init(const float* __restrict__ hidden) {
  int i = blockIdx.x * blockDim.x + threadIdx.x;   // 65536 threads
  if (i < B_ * N_) {
    int b = i >> 10, n = i & 1023;
    float v = __uint_as_float(f2tf(hidden[i]));
    g_hP[0][0][b * N_ + kperm(n)] = v;
    g_hP[0][1][b * N_ + kperm(n)] = v;
  }
  if (i < 2 * T_) g_bar[i] = 0;
}

// Pack U into fragment order (one uint4 per thread).
__global__ void __launch_bounds__(256) k_pack(PU pu) {
  unsigned i = blockIdx.x * 256 + threadIdx.x;
  unsigned lane = i & 31, g = (i >> 5) & 3, ks = (i >> 7) & 3,
           c = (i >> 9) & 3, kq = (i >> 11) & 7, tile = (i >> 14) & 63,
           dir = (i >> 20) & 1;
  int g4 = lane >> 2, tq = lane & 3;
  int row = tile * 16 + g4;
  int k = kq * 128 + c * 32 + ks * 8 + tq;
  const float* U = pu.U[dir * 4 + g];
  uint4 o;
  o.x = f2tf(U[(size_t)row * N_ + k]);
  o.y = f2tf(U[(size_t)(row + 8) * N_ + k]);
  o.z = f2tf(U[(size_t)row * N_ + k + 4]);
  o.w = f2tf(U[(size_t)(row + 8) * N_ + k + 4]);
  g_Upk[i] = o;
}

// ---------------- Phase 1: G[dg][t][b][n] = sum_m x[t_src,b,m] * W[m,n] ----
// Tile 128 rows (2 timesteps x 64 batch) x 256 n-cols, K-chunks of 32,
// cp.async double-buffered. 512 thr = 16 warps (4 wm x 4 wn), warp 32x64.
// dyn smem (floats): A[2][128][36] at 0 (per-buf 4608), B[2][32][264] at
// 9216 (per-buf 8448). total 26112 fl = 104448 B.
#define GA_STR 4608
#define GB_OFF 9216
#define GB_STR 8448
#define GSM_BYTES 104448

__global__ void __launch_bounds__(512) k_gemm_xw(const float* __restrict__ x, PW pw) {
  extern __shared__ float gsm[];
  uint32_t smb = (uint32_t)__cvta_generic_to_shared(gsm);
  int tid = threadIdx.x;
  int wid = tid >> 5, lane = tid & 31;
  int g4 = lane >> 2, tq = lane & 3;
  int wm = wid & 3, wn = wid >> 2;
  int n0 = blockIdx.x * 256;
  int tp = blockIdx.y;                     // timestep pair
  int dg = blockIdx.z;
  int dir = dg / 3;
  int ts0 = dir ? (T_ - 1 - 2 * tp) : (2 * tp);         // x index, row<64
  int ts1 = dir ? (T_ - 2 - 2 * tp) : (2 * tp + 1);     // x index, row>=64
  const float* W = pw.p[dg];
  const float* xt0 = x + (size_t)ts0 * (B_ * M_);
  const float* xt1 = x + (size_t)ts1 * (B_ * M_);

  // issue K-chunk c (32 k) into buffer buf
  auto issue = [&](int c, int buf) {
    #pragma unroll
    for (int j = 0; j < 2; j++) {          // A: 128 rows x 32 k = 1024 float4
      int unit = tid + j * 512;
      int row = unit >> 3, f4 = (unit & 7) << 2;
      const float* base = (row & 64) ? xt1 : xt0;
      cpa16(smb + (buf * GA_STR + row * 36 + f4) * 4,
            base + (row & 63) * M_ + c * 32 + f4);
    }
    #pragma unroll
    for (int j = 0; j < 4; j++) {          // B: 32 k x 256 n = 2048 float4
      int unit = tid + j * 512;
      int kr = unit >> 6, f4 = (unit & 63) << 2;
      cpa16(smb + (GB_OFF + buf * GB_STR + kr * 264 + f4) * 4,
            W + (size_t)(c * 32 + kr) * N_ + n0 + f4);
    }
    asm volatile("cp.async.commit_group;");
  };

  float acc[2][8][4];
  #pragma unroll
  for (int a = 0; a < 2; a++)
    #pragma unroll
    for (int b = 0; b < 8; b++)
      #pragma unroll
      for (int cc = 0; cc < 4; cc++) acc[a][b][cc] = 0.f;

  issue(0, 0);
  #pragma unroll 1
  for (int c = 0; c < 16; ++c) {
    if (c < 15) {
      issue(c + 1, (c + 1) & 1);
      asm volatile("cp.async.wait_group 1;");
    } else {
      asm volatile("cp.async.wait_group 0;");
    }
    __syncthreads();
    const float* As = gsm + (c & 1) * GA_STR;
    const float* Bs = gsm + GB_OFF + (c & 1) * GB_STR;
    #pragma unroll
    for (int ks = 0; ks < 32; ks += 8) {
      uint32_t af[2][4];
      #pragma unroll
      for (int mt = 0; mt < 2; mt++) {
        int r = wm * 32 + mt * 16 + g4;
        af[mt][0] = f2tf(As[r * 36 + ks + tq]);
        af[mt][1] = f2tf(As[(r + 8) * 36 + ks + tq]);
        af[mt][2] = f2tf(As[r * 36 + ks + tq + 4]);
        af[mt][3] = f2tf(As[(r + 8) * 36 + ks + tq + 4]);
      }
      #pragma unroll
      for (int nt = 0; nt < 8; nt++) {
        int ccol = wn * 64 + nt * 8 + g4;
        uint32_t b0 = f2tf(Bs[(ks + tq) * 264 + ccol]);
        uint32_t b1 = f2tf(Bs[(ks + tq + 4) * 264 + ccol]);
        #pragma unroll
        for (int mt = 0; mt < 2; mt++)
          mma8(acc[mt][nt], af[mt][0], af[mt][1], af[mt][2], af[mt][3], b0, b1);
      }
    }
    __syncthreads();
  }
  // store: row r -> (t_idx = 2*tp + (r>>6), b = r&63); col -> n
  #pragma unroll
  for (int mt = 0; mt < 2; mt++) {
    int brow = wm * 32 + mt * 16 + g4;
    int t_idx = 2 * tp + (brow >> 6);
    int bb = brow & 63;
    size_t gb = (size_t)(dg * T_ + t_idx) * (N_ * B_) + (size_t)bb * N_;
    #pragma unroll
    for (int nt = 0; nt < 8; nt++) {
      int nc = n0 + wn * 64 + nt * 8 + 2 * tq;
      *(float2*)&g_G[gb + nc] = make_float2(acc[mt][nt][0], acc[mt][nt][1]);
    }
    int brow2 = brow + 8;
    int t_idx2 = 2 * tp + (brow2 >> 6);
    int bb2 = brow2 & 63;
    size_t gb2 = (size_t)(dg * T_ + t_idx2) * (N_ * B_) + (size_t)bb2 * N_;
    #pragma unroll
    for (int nt = 0; nt < 8; nt++) {
      int nc = n0 + wn * 64 + nt * 8 + 2 * tq;
      *(float2*)&g_G[gb2 + nc] = make_float2(acc[mt][nt][2], acc[mt][nt][3]);
    }
  }
}

// ---------------- Phase 2: persistent recurrent kernel (exact R9) ----------
#define BUFW 2560                  // 64 * 40 words per chunk buffer
#define PAIRW 5120                 // 2 buffers
#define SMEM_BYTES (8 * PAIRW * 4) // 163840
#define ZS(q, r, cl) ((q) * PAIRW + (r) * 66 + (cl))

__global__ void __launch_bounds__(512) k_recur(PU pu, float* __restrict__ out) {
  extern __shared__ float sm[];
  uint32_t smb = (uint32_t)__cvta_generic_to_shared(sm);
  int tid = threadIdx.x, wid = tid >> 5, lane = tid & 31;
  int g4 = lane >> 2, tq = lane & 3;
  int dir = blockIdx.x >> 6, tile = blockIdx.x & 63, rn = tile << 4;
  int rg = wid & 1, kq = wid >> 1;
  int pt = rg * 32 + lane;                 // pair-local tid 0..63
  int barid = 1 + kq;

  const uint4* upk = g_Upk + (((size_t)dir * 64 + tile) << 14)
                     + kq * 2048 + 2 * rg * 32 + lane;
  uint32_t pair_smb = smb + kq * PAIRW * 4;

  int b_e = tid >> 3;
  int nn = (tid & 7) << 1;

  float bia[4][2];
  #pragma unroll
  for (int g = 0; g < 4; g++) {
    bia[g][0] = pu.bia[dir * 4 + g][rn + nn];
    bia[g][1] = pu.bia[dir * 4 + g][rn + nn + 1];
  }
  const float* Gb0 = g_G + (size_t)(dir * 3 + 0) * T_ * N_ * B_;
  const float* Gb1 = g_G + (size_t)(dir * 3 + 1) * T_ * N_ * B_;
  const float* Gb2 = g_G + (size_t)(dir * 3 + 2) * T_ * N_ * B_;
  int hslot0 = kperm(rn + nn), hslot1 = kperm(rn + nn + 1);
  unsigned* barp = &g_bar[dir * T_];

  float creg[2] = {0.f, 0.f};

  uint4 A0 = __ldg(upk), A1 = __ldg(upk + 32);

  for (int s = 0; s < T_; ++s) {
    const float* hsrc = g_hP[s & 1][dir];
    const float* hkq = hsrc + kq * 128;

    #pragma unroll
    for (int c0 = 0; c0 < 2; c0++) {
      #pragma unroll
      for (int j = 0; j < 8; j++) {
        int unit = pt + j * 64;
        int b = unit >> 3, seg = unit & 7;
        cpa16(pair_smb + (c0 * BUFW + b * 40 + seg * 4) * 4,
              hkq + b * N_ + c0 * 32 + seg * 4);
      }
      asm volatile("cp.async.commit_group;");
    }

    size_t goff = ((size_t)s * B_ + b_e) * N_ + rn + nn;
    float2 gq0 = __ldg((const float2*)(Gb0 + goff));
    float2 gq1 = __ldg((const float2*)(Gb1 + goff));
    float2 gq2 = __ldg((const float2*)(Gb2 + goff));

    float acc[2][8][4];
    #pragma unroll
    for (int m = 0; m < 2; m++)
      #pragma unroll
      for (int nt = 0; nt < 8; nt++)
        #pragma unroll
        for (int cc = 0; cc < 4; cc++) acc[m][nt][cc] = 0.f;

    #pragma unroll
    for (int t = 0; t < 16; ++t) {
      int c = t >> 2;
      if ((t & 3) == 0) {
        if (c < 3) asm volatile("cp.async.wait_group 1;");
        else       asm volatile("cp.async.wait_group 0;");
        barp64(barid);
      }
      int tn = (t + 1) & 15;
      const uint4* upn = upk + ((tn >> 2) * 512 + (tn & 3) * 128);
      uint4 An0 = __ldg(upn), An1 = __ldg(upn + 32);

      const float* bb = sm + kq * PAIRW + ((t >> 2) & 1) * BUFW
                        + (t & 3) * 8 + 2 * tq;
      #pragma unroll
      for (int nt = 0; nt < 8; ++nt) {
        uint2 Bv = *(const uint2*)(bb + (nt * 8 + g4) * 40);
        mma8(acc[0][nt], A0.x, A0.y, A0.z, A0.w, Bv.x, Bv.y);
        mma8(acc[1][nt], A1.x, A1.y, A1.z, A1.w, Bv.x, Bv.y);
      }
      A0 = An0; A1 = An1;

      if ((t & 3) == 3 && c < 2) {
        barp64(barid);
        int cn = c + 2;
        #pragma unroll
        for (int j = 0; j < 8; j++) {
          int unit = pt + j * 64;
          int b = unit >> 3, seg = unit & 7;
          cpa16(pair_smb + ((c & 1) * BUFW + b * 40 + seg * 4) * 4,
                hkq + b * N_ + cn * 32 + seg * 4);
        }
        asm volatile("cp.async.commit_group;");
      }
    }

    barp64(barid);

    #pragma unroll
    for (int m = 0; m < 2; m++) {
      int gate = 2 * rg + m;
      #pragma unroll
      for (int nt = 0; nt < 8; nt++) {
        int cl = nt * 8 + 2 * tq;
        *(float2*)&sm[ZS(kq, gate * 16 + g4, cl)] =
            make_float2(acc[m][nt][0], acc[m][nt][1]);
        *(float2*)&sm[ZS(kq, gate * 16 + g4 + 8, cl)] =
            make_float2(acc[m][nt][2], acc[m][nt][3]);
      }
    }
    __syncthreads();

    float z[4][2];
    #pragma unroll
    for (int g = 0; g < 4; g++) {
      #pragma unroll
      for (int e = 0; e < 2; e++) {
        float zz = bia[g][e];
        #pragma unroll
        for (int q = 0; q < 8; q++) zz += sm[ZS(q, g * 16 + nn + e, b_e)];
        z[g][e] = zz;
      }
    }
    float* hdst = g_hP[(s + 1) & 1][dir];
    int t_out = dir ? (T_ - 1 - s) : s;
    float2 ho;
    #pragma unroll
    for (int e = 0; e < 2; e++) {
      float gf = e ? gq0.y : gq0.x;
      float gi = e ? gq1.y : gq1.x;
      float gc = e ? gq2.y : gq2.x;
      float zf = z[0][e] + gf, zi = z[1][e] + gi;
      float zc = z[2][e] + gc, zo = z[3][e] + gf;   // o reuses gf (ref bug)
      float f  = sigm_f(zf);
      float ig = sigm_f(zi);
      float o  = sigm_f(zo);
      float cn = f * creg[e] + ig * tanh_f(zc);
      creg[e] = cn;
      float h = o * tanh_f(cn);
      ((float*)&ho)[e] = h;
      __stcg(hdst + b_e * N_ + (e ? hslot1 : hslot0), __uint_as_float(f2tf(h)));
    }
    *(float2*)(out + ((size_t)t_out * B_ + b_e) * (2 * N_) +
               (size_t)dir * N_ + rn + nn) = ho;

    if (s < T_ - 1) {
      __syncthreads();
      if (tid == 0) {
        unsigned v;
        asm volatile("atom.add.acq_rel.gpu.global.u32 %0, [%1], 1;"
                     : "=r"(v) : "l"(&barp[s]) : "memory");
        if (v + 1u < NBD) {
          unsigned w;
          do {
            asm volatile("ld.acquire.gpu.global.u32 %0, [%1];"
                         : "=r"(w) : "l"(&barp[s]) : "memory");
            if (w >= NBD) break;
            __nanosleep(32);
          } while (true);
        }
      }
      __syncthreads();
    }
  }
}

extern "C" void kernel_launch(void* const* d_in, const int* in_sizes, int n_in,
                              void* d_out, int out_size) {
  const float* x      = (const float*)d_in[0];
  const float* hidden = (const float*)d_in[1];
  PW pw;
  pw.p[0] = (const float*)d_in[2];   // Wf1
  pw.p[1] = (const float*)d_in[3];   // Wi1
  pw.p[2] = (const float*)d_in[4];   // Wc1
  pw.p[3] = (const float*)d_in[13];  // Wf2
  pw.p[4] = (const float*)d_in[14];  // Wi2
  pw.p[5] = (const float*)d_in[15];  // Wc2

  PU pu;  // gate order f,i,c,o
  pu.U[0] = (const float*)d_in[5];   // Uf1
  pu.U[1] = (const float*)d_in[6];   // Ui1
  pu.U[2] = (const float*)d_in[8];   // Uc1
  pu.U[3] = (const float*)d_in[7];   // Uo1
  pu.U[4] = (const float*)d_in[16];  // Uf2
  pu.U[5] = (const float*)d_in[17];  // Ui2
  pu.U[6] = (const float*)d_in[19];  // Uc2
  pu.U[7] = (const float*)d_in[18];  // Uo2
  pu.bia[0] = (const float*)d_in[9];   // bf1
  pu.bia[1] = (const float*)d_in[10];  // bi1
  pu.bia[2] = (const float*)d_in[12];  // bc1
  pu.bia[3] = (const float*)d_in[11];  // bo1
  pu.bia[4] = (const float*)d_in[20];  // bf2
  pu.bia[5] = (const float*)d_in[21];  // bi2
  pu.bia[6] = (const float*)d_in[23];  // bc2
  pu.bia[7] = (const float*)d_in[22];  // bo2

  static int smem_set = 0;
  if (!smem_set) {
    cudaFuncSetAttribute(k_recur, cudaFuncAttributeMaxDynamicSharedMemorySize,
                         SMEM_BYTES);
    cudaFuncSetAttribute(k_gemm_xw, cudaFuncAttributeMaxDynamicSharedMemorySize,
                         GSM_BYTES);
    smem_set = 1;
  }

  k_init<<<256, 256>>>(hidden);
  k_pack<<<8192, 256>>>(pu);
  k_gemm_xw<<<dim3(4, 128, 6), 512, GSM_BYTES>>>(x, pw);
  k_recur<<<NB_REC, 512, SMEM_BYTES>>>(pu, (float*)d_out);
}